// round 11
// baseline (speedup 1.0000x reference)
#include <cuda_runtime.h>
#include <cuda_fp16.h>
#include <cstdint>

#define FF 40
#define DD 768
#define HH 256
#define MAXP 780           // F*(F-1)/2
#define PPAD 832           // 13*64, >= MAXP, multiple of 64
#define BT_TOTAL (64*256)
#define KC 32

// ---------------- device scratch (no allocations allowed) ----------------
__device__ __align__(16) __half g_EWT[HH * PPAD];       // [h][p] fp16
__device__ __align__(16) unsigned long long g_pm[PPAD]; // compacted pair masks
__device__ __align__(16) unsigned long long g_avr[FF];  // avail row bits (j>i)
__device__ int g_Pg;

__device__ __forceinline__ uint32_t smem_u32(const void* p) {
    return (uint32_t)__cvta_generic_to_shared(p);
}

// closed-form upper-triangular decode: L -> (i, j), base(i) = i*(79-i)/2
__device__ __forceinline__ void pair_decode(int L, int& i, int& j) {
    i = (int)((79.0f - sqrtf((float)(6241 - 8 * L))) * 0.5f);
    while (i * (79 - i) / 2 > L) --i;
    while ((i + 1) * (78 - i) / 2 <= L) ++i;
    j = i + 1 + (L - i * (79 - i) / 2);
}

// ---------------- 1) ew_kernel: EWT[h,p] = sum_d E[i_p,j_p,d]*W[h,d] (fp32->fp16) ----
// grid (104, 8) x 64 threads, ONE 8p x 32h tile per block.
// Every block recomputes the compaction; block (0,0) publishes g_pm/g_avr/g_Pg.
__global__ void __launch_bounds__(64) ew_kernel(const float* __restrict__ E,
                                                const float* __restrict__ W,
                                                const void* __restrict__ avail) {
    __shared__ __align__(16) float sE[8][36];    // 144B pitch: rows stay 16B-aligned
    __shared__ __align__(16) float sW[32][36];
    __shared__ unsigned char s_av[FF * FF];
    __shared__ unsigned int s_words[26];
    __shared__ int s_wpre[27];
    __shared__ int s_P;
    __shared__ int s_rb[8];

    int t = threadIdx.x;

    // avail dtype: u8 packs random 0/1 bytes -> words outside the valid set
    int okA = 1;
    for (int i = t; i < 400; i += 64) {
        unsigned int v = ((const unsigned int*)avail)[i];
        okA &= (v == 0u) | (v == 1u) | (v == 0x3F800000u);
    }
    okA = __syncthreads_and(okA);
    if (okA) { for (int i = t; i < FF * FF; i += 64) s_av[i] = ((const unsigned int*)avail)[i] != 0u; }
    else     { for (int i = t; i < FF * FF; i += 64) s_av[i] = ((const unsigned char*)avail)[i] != 0; }
    __syncthreads();

    // flags -> 26 ballot words (L = r*64 + t)
    #pragma unroll
    for (int r = 0; r < 13; ++r) {
        int L = r * 64 + t;
        int f = 0;
        if (L < MAXP) {
            int i, j; pair_decode(L, i, j);
            f = s_av[i * FF + j];
        }
        unsigned int bal = __ballot_sync(0xffffffffu, f);
        if ((t & 31) == 0) s_words[r * 2 + (t >> 5)] = bal;
    }
    __syncthreads();
    if (t == 0) {
        int s = 0;
        for (int w = 0; w < 26; ++w) { s_wpre[w] = s; s += __popc(s_words[w]); }
        s_wpre[26] = s; s_P = s;
    }
    __syncthreads();
    int P = s_P;
    int nch64 = (P + 63) >> 6; if (nch64 < 1) nch64 = 1;
    int plim = nch64 * 64;

    // block (0,0) publishes tables for gemm
    if (blockIdx.x == 0 && blockIdx.y == 0) {
        if (t == 0) g_Pg = P;
        if (t < FF) {
            unsigned long long r = 0ull;
            for (int j = t + 1; j < FF; ++j)
                if (s_av[t * FF + j]) r |= 1ull << j;
            g_avr[t] = r;
        }
        for (int L = t; L < PPAD; L += 64) {
            if (L < MAXP && ((s_words[L >> 5] >> (L & 31)) & 1u)) {
                int pos = s_wpre[L >> 5] +
                          __popc(s_words[L >> 5] & ((1u << (L & 31)) - 1u));
                int i, j; pair_decode(L, i, j);
                g_pm[pos] = (1ull << i) | (1ull << j);
            }
            if (L >= P) g_pm[L] = ~0ull;
        }
    }

    int p0 = blockIdx.x * 8;
    int h0 = blockIdx.y * 32;
    if (p0 >= plim) return;                          // never read by gemm
    if (p0 >= P) {                                   // pad rows inside read window
        for (int q = t; q < 32 * 4; q += 64) {
            int hcz = q >> 2, pq = q & 3;
            *(unsigned int*)&g_EWT[(h0 + hcz) * PPAD + p0 + pq * 2] = 0u;
        }
        return;
    }

    if (t < 8) {
        int p = p0 + t;
        int rb = -1;
        if (p < P) {         // find p-th set flag
            int w = 0;
            while (s_wpre[w + 1] <= p) ++w;
            unsigned int word = s_words[w];
            int rem = p - s_wpre[w];
            for (int q = 0; q < rem; ++q) word &= word - 1;
            int L = w * 32 + (__ffs(word) - 1);
            int i, j; pair_decode(L, i, j);
            rb = (i * FF + j) * DD;
        }
        s_rb[t] = rb;
    }
    __syncthreads();

    const int erow = t >> 3, ekq = t & 7;
    const int ebase = s_rb[erow];
    const int prow = (t >> 4) * 2;
    const int hc = t & 15;

    float4 re, rw[4];
    re = make_float4(0.f, 0.f, 0.f, 0.f);
    if (ebase >= 0) re = *(const float4*)(E + ebase + ekq * 4);
    #pragma unroll
    for (int r = 0; r < 4; ++r) {
        int idx = t + 64 * r;
        int row = idx >> 3, kq = idx & 7;
        rw[r] = *(const float4*)(W + (size_t)(h0 + row) * DD + kq * 4);
    }

    float a00 = 0.f, a01 = 0.f, a10 = 0.f, a11 = 0.f;
    for (int c = 0; c < DD / 32; ++c) {
        __syncthreads();
        *(float4*)&sE[erow][ekq * 4] = re;
        #pragma unroll
        for (int r = 0; r < 4; ++r) {
            int idx = t + 64 * r;
            int row = idx >> 3, kq = idx & 7;
            *(float4*)&sW[row][kq * 4] = rw[r];
        }
        __syncthreads();
        if (c + 1 < DD / 32) {
            int k0 = (c + 1) * 32;
            re = make_float4(0.f, 0.f, 0.f, 0.f);
            if (ebase >= 0) re = *(const float4*)(E + ebase + k0 + ekq * 4);
            #pragma unroll
            for (int r = 0; r < 4; ++r) {
                int idx = t + 64 * r;
                int row = idx >> 3, kq = idx & 7;
                rw[r] = *(const float4*)(W + (size_t)(h0 + row) * DD + k0 + kq * 4);
            }
        }
        #pragma unroll
        for (int kk = 0; kk < 32; kk += 4) {
            float4 e0 = *(float4*)&sE[prow][kk];
            float4 e1 = *(float4*)&sE[prow + 1][kk];
            float4 w0 = *(float4*)&sW[hc][kk];
            float4 w1 = *(float4*)&sW[hc + 16][kk];
            a00 += e0.x * w0.x + e0.y * w0.y + e0.z * w0.z + e0.w * w0.w;
            a01 += e0.x * w1.x + e0.y * w1.y + e0.z * w1.z + e0.w * w1.w;
            a10 += e1.x * w0.x + e1.y * w0.y + e1.z * w0.z + e1.w * w0.w;
            a11 += e1.x * w1.x + e1.y * w1.y + e1.z * w1.z + e1.w * w1.w;
        }
    }
    int pA = p0 + prow, pB = pA + 1;
    g_EWT[(h0 + hc) * PPAD + pA]      = __float2half_rn(a00);
    g_EWT[(h0 + hc + 16) * PPAD + pA] = __float2half_rn(a01);
    g_EWT[(h0 + hc) * PPAD + pB]      = __float2half_rn(a10);
    g_EWT[(h0 + hc + 16) * PPAD + pB] = __float2half_rn(a11);
}

// ---------------- 2) mma.sync GEMM: out = (sel @ EW) * (1/cnt) + bias ----------------
// BM=32, BN=256, KC=32; 256 threads = 8 warps as 2m x 4n, warp tile 16m x 64n.
// ~48KB smem/CTA -> 4 CTAs/SM; grid 512 -> ~3.5 CTAs/SM, 28 warps/SM.
#define ABYTES 4096                  // 32 rows x 128B pitch
#define BBYTES 16384                 // 256 rows x 64B pitch
#define BUFB (ABYTES + BBYTES)       // 20 KB
#define DSMEM_BYTES (2 * BUFB + 128)

#define LDSM4(r0, r1, r2, r3, addr) \
    asm volatile("ldmatrix.sync.aligned.m8n8.x4.shared.b16 {%0,%1,%2,%3}, [%4];" \
                 : "=r"(r0), "=r"(r1), "=r"(r2), "=r"(r3) : "r"(addr))

#define MMA_F16(d, a, b0v, b1v) \
    asm volatile("mma.sync.aligned.m16n8k16.row.col.f32.f16.f16.f32 " \
                 "{%0,%1,%2,%3}, {%4,%5,%6,%7}, {%8,%9}, {%0,%1,%2,%3};" \
                 : "+f"((d)[0]), "+f"((d)[1]), "+f"((d)[2]), "+f"((d)[3]) \
                 : "r"((a)[0]), "r"((a)[1]), "r"((a)[2]), "r"((a)[3]), \
                   "r"(b0v), "r"(b1v))

__global__ void __launch_bounds__(256)
gemm_kernel(const unsigned int* __restrict__ mask_w,
            const float* __restrict__ bias, float* __restrict__ out) {
    extern __shared__ char dyn_raw[];
    __shared__ __align__(16) unsigned long long s_pm[PPAD];
    __shared__ __align__(16) unsigned long long s_bits[32];
    __shared__ __align__(16) unsigned long long s_avr[FF];
    __shared__ __align__(16) float s_scale[32];
    __shared__ __align__(16) float s_bias[HH];

    uint32_t raw = smem_u32(dyn_raw);
    uint32_t base = (raw + 127u) & ~127u;
    char* dynp = dyn_raw + (base - raw);

    const int t = threadIdx.x;
    const int lane = t & 31, wid = t >> 5;
    const int wm = (wid & 1) * 16;      // 2 m-groups of 16 rows
    const int wn = (wid >> 1) * 64;     // 4 n-groups of 64 cols
    const int m0 = blockIdx.x * 32;

    // ---- B chunk via cp.async (fp16): 256 rows x 32 k, 64B row pitch ----
    #define ISSUE_B(c, bufbase) do {                                               \
        _Pragma("unroll")                                                          \
        for (int r = 0; r < 4; ++r) {                                              \
            int idx = t + r * 256;                                                 \
            int row = idx >> 2, kc = idx & 3;                                      \
            const __half* src = g_EWT + (size_t)row * PPAD + (c) * KC + kc * 8;    \
            uint32_t dst = (bufbase) + ABYTES + row * 64 + ((kc ^ (row & 3)) << 4); \
            asm volatile("cp.async.cg.shared.global [%0], [%1], 16;"               \
                         :: "r"(dst), "l"(src));                                   \
        }                                                                          \
        asm volatile("cp.async.commit_group;" ::: "memory");                       \
    } while (0)

    // ---- A (sel, fp16 1.0) chunk: 32 rows x 32 k, 128B row pitch ----
    #define BUILD_A(c, bufbase) do {                                               \
        if (t < 128) {                                                             \
            int m = t >> 2, kc = t & 3;                                            \
            unsigned long long bb = s_bits[m];                                     \
            int pb = (c) * KC + kc * 8;                                            \
            unsigned long long q0 = s_pm[pb+0], q1 = s_pm[pb+1];                   \
            unsigned long long q2 = s_pm[pb+2], q3 = s_pm[pb+3];                   \
            unsigned long long q4 = s_pm[pb+4], q5 = s_pm[pb+5];                   \
            unsigned long long q6 = s_pm[pb+6], q7 = s_pm[pb+7];                   \
            uint32_t w0 = (((bb & q0) == q0) ? 0x3C00u : 0u) |                     \
                          (((bb & q1) == q1) ? 0x3C000000u : 0u);                  \
            uint32_t w1 = (((bb & q2) == q2) ? 0x3C00u : 0u) |                     \
                          (((bb & q3) == q3) ? 0x3C000000u : 0u);                  \
            uint32_t w2 = (((bb & q4) == q4) ? 0x3C00u : 0u) |                     \
                          (((bb & q5) == q5) ? 0x3C000000u : 0u);                  \
            uint32_t w3 = (((bb & q6) == q6) ? 0x3C00u : 0u) |                     \
                          (((bb & q7) == q7) ? 0x3C000000u : 0u);                  \
            uint32_t dst = (bufbase) + m * 128 + ((kc ^ (m & 7)) << 4);            \
            asm volatile("st.shared.v4.b32 [%0], {%1,%2,%3,%4};"                   \
                         :: "r"(dst), "r"(w0), "r"(w1), "r"(w2), "r"(w3));         \
        }                                                                          \
    } while (0)

    ISSUE_B(0, base);

    // ---- prologue: global tables + per-CTA mask bits (coalesced stage) ----
    int P = g_Pg;
    int nch = (P + KC - 1) / KC; if (nch < 1) nch = 1;
    for (int i = t; i < PPAD; i += 256) s_pm[i] = g_pm[i];
    if (t < FF) s_avr[t] = g_avr[t];
    if (t < HH) s_bias[t] = bias[t];

    // mask dtype: u8 packs random 0/1 bytes -> words outside the valid set
    int okM;
    {
        unsigned int v0 = mask_w[t], v1 = mask_w[t + 256];
        int ok = ((v0 == 0u) | (v0 == 1u) | (v0 == 0x3F800000u)) &
                 ((v1 == 0u) | (v1 == 1u) | (v1 == 0x3F800000u));
        okM = __syncthreads_and(ok);
    }
    {
        unsigned int* stage = (unsigned int*)(dynp + BUFB);   // buf1, idle until c=1
        if (okM) {      // 32-bit elements: 32 rows x 40 words
            for (int idx = t; idx < 1280; idx += 256)
                stage[idx] = mask_w[(size_t)m0 * 40 + idx];
        } else {        // u8: 32 rows x 10 words
            if (t < 320) stage[t] = mask_w[(size_t)m0 * 10 + t];
        }
        __syncthreads();
        if (t < 32) {
            unsigned long long b = 0ull;
            if (okM) {
                const unsigned int* rp = stage + t * 40;
                #pragma unroll
                for (int f = 0; f < FF; ++f)
                    if (rp[f]) b |= 1ull << f;
            } else {
                const unsigned int* rp = stage + t * 10;
                #pragma unroll
                for (int wi = 0; wi < 10; ++wi) {
                    unsigned int w = rp[wi];
                    #pragma unroll
                    for (int by = 0; by < 4; ++by)
                        if ((w >> (by * 8)) & 0xFFu) b |= 1ull << (wi * 4 + by);
                }
            }
            s_bits[t] = b;
            int cnt = 0;
            unsigned long long x = b;
            while (x) {
                int i = __ffsll((long long)x) - 1;
                x &= x - 1;
                cnt += __popcll(s_avr[i] & b);
            }
            s_scale[t] = (cnt > 0) ? (1.0f / (float)cnt) : 0.0f;
        }
        __syncthreads();
    }

    float acc[8][4];
    #pragma unroll
    for (int j = 0; j < 8; ++j)
        #pragma unroll
        for (int q = 0; q < 4; ++q) acc[j][q] = 0.f;

    BUILD_A(0, base);
    asm volatile("cp.async.wait_group 0;" ::: "memory");
    __syncthreads();

    for (int c = 0; c < nch; ++c) {
        uint32_t cur = base + (c & 1) * BUFB;
        if (c + 1 < nch) {
            uint32_t nxt = base + ((c + 1) & 1) * BUFB;
            ISSUE_B(c + 1, nxt);
            BUILD_A(c + 1, nxt);
        }
        uint32_t Ab = cur, Bb = cur + ABYTES;
        #pragma unroll
        for (int ks = 0; ks < 2; ++ks) {
            uint32_t a[4];
            {
                int arow = wm + (lane & 7) + ((lane >> 3) & 1) * 8;
                int akc = ks * 2 + (lane >> 4);
                uint32_t ad = Ab + arow * 128 + ((akc ^ (arow & 7)) << 4);
                LDSM4(a[0], a[1], a[2], a[3], ad);
            }
            #pragma unroll
            for (int nb2 = 0; nb2 < 4; ++nb2) {
                int brow = wn + nb2 * 16 + (lane & 7) + (lane >> 4) * 8;
                int bkc = ks * 2 + ((lane >> 3) & 1);
                uint32_t off = brow * 64 + ((bkc ^ (brow & 3)) << 4);
                uint32_t b0, b1, b2, b3;
                LDSM4(b0, b1, b2, b3, Bb + off);
                MMA_F16(acc[nb2 * 2 + 0], a, b0, b1);
                MMA_F16(acc[nb2 * 2 + 1], a, b2, b3);
            }
        }
        if (c + 1 < nch) {
            asm volatile("cp.async.wait_group 0;" ::: "memory");
        }
        __syncthreads();
    }

    // ---- epilogue: scale by 1/cnt, add bias, store ----
    {
        int rl = wm + (lane >> 2);
        int row0 = m0 + rl;
        float sc0 = s_scale[rl];
        float sc1 = s_scale[rl + 8];
        #pragma unroll
        for (int nf = 0; nf < 8; ++nf) {
            int col = wn + (nf >> 1) * 16 + (nf & 1) * 8 + 2 * (lane & 3);
            float bv0 = s_bias[col], bv1 = s_bias[col + 1];
            float2 o0, o1;
            o0.x = acc[nf][0] * sc0 + bv0;
            o0.y = acc[nf][1] * sc0 + bv1;
            o1.x = acc[nf][2] * sc1 + bv0;
            o1.y = acc[nf][3] * sc1 + bv1;
            *(float2*)(out + (size_t)row0 * HH + col) = o0;
            *(float2*)(out + (size_t)(row0 + 8) * HH + col) = o1;
        }
    }
}

// ---------------- launch ----------------
extern "C" void kernel_launch(void* const* d_in, const int* in_sizes, int n_in,
                              void* d_out, int out_size) {
    const void* mask = d_in[0];                    // [64,256,40] bool
    const float* E = (const float*)d_in[1];        // [40,40,768] f32
    const void* avail = (const void*)d_in[2];      // [40,40] bool
    const float* W = (const float*)d_in[3];        // [256,768] f32
    const float* bias = (const float*)d_in[4];     // [256] f32
    float* out = (float*)d_out;                    // [64,256,256] f32

    cudaFuncSetAttribute(gemm_kernel, cudaFuncAttributeMaxDynamicSharedMemorySize,
                         DSMEM_BYTES);

    ew_kernel<<<dim3(104, 8), 64>>>(E, W, avail);
    gemm_kernel<<<BT_TOTAL / 32, 256, DSMEM_BYTES>>>((const unsigned int*)mask,
                                                     bias, out);
}

// round 12
// speedup vs baseline: 1.1578x; 1.1578x over previous
#include <cuda_runtime.h>
#include <cuda_fp16.h>
#include <cstdint>

#define FF 40
#define DD 768
#define HH 256
#define MAXP 780           // F*(F-1)/2
#define PPAD 832           // 13*64, >= MAXP, multiple of 64
#define BT_TOTAL (64*256)
#define KC 64

// ---------------- device scratch (no allocations allowed) ----------------
__device__ __align__(16) __half g_EWT[HH * PPAD];       // [h][p] fp16
__device__ __align__(16) unsigned long long g_pm[PPAD]; // compacted pair masks
__device__ __align__(16) unsigned long long g_bits[BT_TOTAL];
__device__ __align__(16) float g_scale[BT_TOTAL];
__device__ int g_Pg;

__device__ __forceinline__ uint32_t smem_u32(const void* p) {
    return (uint32_t)__cvta_generic_to_shared(p);
}

// closed-form upper-triangular decode: L -> (i, j), base(i) = i*(79-i)/2
__device__ __forceinline__ void pair_decode(int L, int& i, int& j) {
    i = (int)((79.0f - sqrtf((float)(6241 - 8 * L))) * 0.5f);
    while (i * (79 - i) / 2 > L) --i;
    while ((i + 1) * (78 - i) / 2 <= L) ++i;
    j = i + 1 + (L - i * (79 - i) / 2);
}

// ---------------- 1) ew_kernel: EWT + pair tables + mask bits/scale ----------------
// grid (104, 12) x 64 threads.
//   ht = blockIdx.y < 8 : ONE 8p x 32h EW tile (R5-measured shape)
//   ht >= 8             : bits/scale producer, 40 bt-rows per block (416 blocks)
// Every block recomputes the compaction (cheap); block (0,0) publishes g_pm/g_Pg.
__global__ void __launch_bounds__(64) ew_kernel(const float* __restrict__ E,
                                                const float* __restrict__ W,
                                                const void* __restrict__ avail,
                                                const unsigned int* __restrict__ mask_w) {
    __shared__ __align__(16) float sE[8][36];    // 144B pitch: rows stay 16B-aligned
    __shared__ __align__(16) float sW[32][36];
    __shared__ __align__(16) unsigned int stage[1600];  // 40 rows x 40 words
    __shared__ unsigned char s_av[FF * FF];
    __shared__ unsigned long long s_avr[FF];
    __shared__ unsigned int s_words[26];
    __shared__ int s_wpre[27];
    __shared__ int s_P;
    __shared__ int s_rb[8];

    int t = threadIdx.x;
    int ht = blockIdx.y;

    // avail dtype: u8 packs random 0/1 bytes -> words outside the valid set
    int okA = 1;
    for (int i = t; i < 400; i += 64) {
        unsigned int v = ((const unsigned int*)avail)[i];
        okA &= (v == 0u) | (v == 1u) | (v == 0x3F800000u);
    }
    okA = __syncthreads_and(okA);
    if (okA) { for (int i = t; i < FF * FF; i += 64) s_av[i] = ((const unsigned int*)avail)[i] != 0u; }
    else     { for (int i = t; i < FF * FF; i += 64) s_av[i] = ((const unsigned char*)avail)[i] != 0; }
    __syncthreads();

    if (t < FF) {
        unsigned long long r = 0ull;
        for (int j = t + 1; j < FF; ++j)
            if (s_av[t * FF + j]) r |= 1ull << j;
        s_avr[t] = r;
    }

    // flags -> 26 ballot words (L = r*64 + t)
    #pragma unroll
    for (int r = 0; r < 13; ++r) {
        int L = r * 64 + t;
        int f = 0;
        if (L < MAXP) {
            int i, j; pair_decode(L, i, j);
            f = s_av[i * FF + j];
        }
        unsigned int bal = __ballot_sync(0xffffffffu, f);
        if ((t & 31) == 0) s_words[r * 2 + (t >> 5)] = bal;
    }
    __syncthreads();
    if (t == 0) {
        int s = 0;
        for (int w = 0; w < 26; ++w) { s_wpre[w] = s; s += __popc(s_words[w]); }
        s_wpre[26] = s; s_P = s;
    }
    __syncthreads();
    int P = s_P;
    int nch64 = (P + 63) >> 6; if (nch64 < 1) nch64 = 1;
    int plim = nch64 * 64;

    // ======== bits/scale producer blocks ========
    if (ht >= 8) {
        int bb = (ht - 8) * 104 + blockIdx.x;       // 0..415
        int row0 = bb * 40;
        if (row0 >= BT_TOTAL) return;
        int nr = BT_TOTAL - row0; if (nr > 40) nr = 40;

        // mask dtype probe (first 512 words, L2-hot across blocks)
        int okM = 1;
        for (int i = t; i < 512; i += 64) {
            unsigned int v = mask_w[i];
            okM &= (v == 0u) | (v == 1u) | (v == 0x3F800000u);
        }
        okM = __syncthreads_and(okM);

        if (okM) {      // 32-bit elements: nr x 40 words, coalesced
            for (int idx = t; idx < nr * 40; idx += 64)
                stage[idx] = mask_w[(size_t)row0 * 40 + idx];
        } else {        // u8: nr x 10 words
            for (int idx = t; idx < nr * 10; idx += 64)
                stage[idx] = mask_w[(size_t)row0 * 10 + idx];
        }
        __syncthreads();
        if (t < nr) {
            unsigned long long b = 0ull;
            if (okM) {
                const unsigned int* rp = stage + t * 40;
                #pragma unroll
                for (int f = 0; f < FF; ++f)
                    if (rp[f]) b |= 1ull << f;
            } else {
                const unsigned int* rp = stage + t * 10;
                #pragma unroll
                for (int wi = 0; wi < 10; ++wi) {
                    unsigned int w = rp[wi];
                    #pragma unroll
                    for (int by = 0; by < 4; ++by)
                        if ((w >> (by * 8)) & 0xFFu) b |= 1ull << (wi * 4 + by);
                }
            }
            int cnt = 0;
            unsigned long long x = b;
            while (x) {
                int i = __ffsll((long long)x) - 1;
                x &= x - 1;
                cnt += __popcll(s_avr[i] & b);
            }
            g_bits[row0 + t] = b;
            g_scale[row0 + t] = (cnt > 0) ? (1.0f / (float)cnt) : 0.0f;
        }
        return;
    }

    // block (0,0) publishes pair tables for gemm
    if (blockIdx.x == 0 && ht == 0) {
        if (t == 0) g_Pg = P;
        for (int L = t; L < PPAD; L += 64) {
            if (L < MAXP && ((s_words[L >> 5] >> (L & 31)) & 1u)) {
                int pos = s_wpre[L >> 5] +
                          __popc(s_words[L >> 5] & ((1u << (L & 31)) - 1u));
                int i, j; pair_decode(L, i, j);
                g_pm[pos] = (1ull << i) | (1ull << j);
            }
            if (L >= P) g_pm[L] = ~0ull;
        }
    }

    int p0 = blockIdx.x * 8;
    int h0 = ht * 32;
    if (p0 >= plim) return;                          // never read by gemm
    if (p0 >= P) {                                   // pad rows inside read window
        for (int q = t; q < 32 * 4; q += 64) {
            int hcz = q >> 2, pq = q & 3;
            *(unsigned int*)&g_EWT[(h0 + hcz) * PPAD + p0 + pq * 2] = 0u;
        }
        return;
    }

    if (t < 8) {
        int p = p0 + t;
        int rb = -1;
        if (p < P) {         // find p-th set flag
            int w = 0;
            while (s_wpre[w + 1] <= p) ++w;
            unsigned int word = s_words[w];
            int rem = p - s_wpre[w];
            for (int q = 0; q < rem; ++q) word &= word - 1;
            int L = w * 32 + (__ffs(word) - 1);
            int i, j; pair_decode(L, i, j);
            rb = (i * FF + j) * DD;
        }
        s_rb[t] = rb;
    }
    __syncthreads();

    const int erow = t >> 3, ekq = t & 7;
    const int ebase = s_rb[erow];
    const int prow = (t >> 4) * 2;
    const int hc = t & 15;

    float4 re, rw[4];
    re = make_float4(0.f, 0.f, 0.f, 0.f);
    if (ebase >= 0) re = *(const float4*)(E + ebase + ekq * 4);
    #pragma unroll
    for (int r = 0; r < 4; ++r) {
        int idx = t + 64 * r;
        int row = idx >> 3, kq = idx & 7;
        rw[r] = *(const float4*)(W + (size_t)(h0 + row) * DD + kq * 4);
    }

    float a00 = 0.f, a01 = 0.f, a10 = 0.f, a11 = 0.f;
    for (int c = 0; c < DD / 32; ++c) {
        __syncthreads();
        *(float4*)&sE[erow][ekq * 4] = re;
        #pragma unroll
        for (int r = 0; r < 4; ++r) {
            int idx = t + 64 * r;
            int row = idx >> 3, kq = idx & 7;
            *(float4*)&sW[row][kq * 4] = rw[r];
        }
        __syncthreads();
        if (c + 1 < DD / 32) {
            int k0 = (c + 1) * 32;
            re = make_float4(0.f, 0.f, 0.f, 0.f);
            if (ebase >= 0) re = *(const float4*)(E + ebase + k0 + ekq * 4);
            #pragma unroll
            for (int r = 0; r < 4; ++r) {
                int idx = t + 64 * r;
                int row = idx >> 3, kq = idx & 7;
                rw[r] = *(const float4*)(W + (size_t)(h0 + row) * DD + k0 + kq * 4);
            }
        }
        #pragma unroll
        for (int kk = 0; kk < 32; kk += 4) {
            float4 e0 = *(float4*)&sE[prow][kk];
            float4 e1 = *(float4*)&sE[prow + 1][kk];
            float4 w0 = *(float4*)&sW[hc][kk];
            float4 w1 = *(float4*)&sW[hc + 16][kk];
            a00 += e0.x * w0.x + e0.y * w0.y + e0.z * w0.z + e0.w * w0.w;
            a01 += e0.x * w1.x + e0.y * w1.y + e0.z * w1.z + e0.w * w1.w;
            a10 += e1.x * w0.x + e1.y * w0.y + e1.z * w0.z + e1.w * w0.w;
            a11 += e1.x * w1.x + e1.y * w1.y + e1.z * w1.z + e1.w * w1.w;
        }
    }
    int pA = p0 + prow, pB = pA + 1;
    g_EWT[(h0 + hc) * PPAD + pA]      = __float2half_rn(a00);
    g_EWT[(h0 + hc + 16) * PPAD + pA] = __float2half_rn(a01);
    g_EWT[(h0 + hc) * PPAD + pB]      = __float2half_rn(a10);
    g_EWT[(h0 + hc + 16) * PPAD + pB] = __float2half_rn(a11);
}

// ---------------- 2) mma.sync GEMM: out = (sel @ EW) * (1/cnt) + bias ----------------
// BM=64, BN=256, KC=64; 256 threads = 8 warps as 2m x 4n, warp tile 32m x 64n.
// 2 CTAs/SM, pure-load prologue (all tables produced by ew_kernel).
#define ABYTES 8192                  // 64 x 64 fp16
#define BBYTES 32768                 // 256 x 64 fp16
#define BUFB (ABYTES + BBYTES)       // 40 KB
#define DSMEM_BYTES (2 * BUFB + 128)

#define LDSM4(r0, r1, r2, r3, addr) \
    asm volatile("ldmatrix.sync.aligned.m8n8.x4.shared.b16 {%0,%1,%2,%3}, [%4];" \
                 : "=r"(r0), "=r"(r1), "=r"(r2), "=r"(r3) : "r"(addr))

#define MMA_F16(d, a, b0v, b1v) \
    asm volatile("mma.sync.aligned.m16n8k16.row.col.f32.f16.f16.f32 " \
                 "{%0,%1,%2,%3}, {%4,%5,%6,%7}, {%8,%9}, {%0,%1,%2,%3};" \
                 : "+f"((d)[0]), "+f"((d)[1]), "+f"((d)[2]), "+f"((d)[3]) \
                 : "r"((a)[0]), "r"((a)[1]), "r"((a)[2]), "r"((a)[3]), \
                   "r"(b0v), "r"(b1v))

__global__ void __launch_bounds__(256)
gemm_kernel(const float* __restrict__ bias, float* __restrict__ out) {
    extern __shared__ char dyn_raw[];
    __shared__ __align__(16) unsigned long long s_pm[PPAD];
    __shared__ __align__(16) unsigned long long s_bits[64];
    __shared__ __align__(16) float s_scale[64];
    __shared__ __align__(16) float s_bias[HH];

    uint32_t raw = smem_u32(dyn_raw);
    uint32_t base = (raw + 127u) & ~127u;

    const int t = threadIdx.x;
    const int lane = t & 31, wid = t >> 5;
    const int wm = (wid & 1) * 32;      // 2 m-groups of 32 rows
    const int wn = (wid >> 1) * 64;     // 4 n-groups of 64 cols
    const int m0 = blockIdx.x * 64;

    // ---- B chunk via cp.async (fp16), swizzled 16B units ----
    #define ISSUE_B(c, bufbase) do {                                               \
        _Pragma("unroll")                                                          \
        for (int r = 0; r < 8; ++r) {                                              \
            int idx = t + r * 256;                                                 \
            int row = idx >> 3, kc = idx & 7;                                      \
            const __half* src = g_EWT + (size_t)row * PPAD + (c) * KC + kc * 8;    \
            uint32_t dst = (bufbase) + ABYTES + row * 128 + ((kc ^ (row & 7)) << 4); \
            asm volatile("cp.async.cg.shared.global [%0], [%1], 16;"               \
                         :: "r"(dst), "l"(src));                                   \
        }                                                                          \
        asm volatile("cp.async.commit_group;" ::: "memory");                       \
    } while (0)

    #define BUILD_A(c, bufbase) do {                                               \
        _Pragma("unroll")                                                          \
        for (int r = 0; r < 2; ++r) {                                              \
            int idx = t + r * 256;                                                 \
            int m = idx >> 3, kc = idx & 7;                                        \
            unsigned long long bb = s_bits[m];                                     \
            int pb = (c) * KC + kc * 8;                                            \
            unsigned long long q0 = s_pm[pb+0], q1 = s_pm[pb+1];                   \
            unsigned long long q2 = s_pm[pb+2], q3 = s_pm[pb+3];                   \
            unsigned long long q4 = s_pm[pb+4], q5 = s_pm[pb+5];                   \
            unsigned long long q6 = s_pm[pb+6], q7 = s_pm[pb+7];                   \
            uint32_t w0 = (((bb & q0) == q0) ? 0x3C00u : 0u) |                     \
                          (((bb & q1) == q1) ? 0x3C000000u : 0u);                  \
            uint32_t w1 = (((bb & q2) == q2) ? 0x3C00u : 0u) |                     \
                          (((bb & q3) == q3) ? 0x3C000000u : 0u);                  \
            uint32_t w2 = (((bb & q4) == q4) ? 0x3C00u : 0u) |                     \
                          (((bb & q5) == q5) ? 0x3C000000u : 0u);                  \
            uint32_t w3 = (((bb & q6) == q6) ? 0x3C00u : 0u) |                     \
                          (((bb & q7) == q7) ? 0x3C000000u : 0u);                  \
            uint32_t dst = (bufbase) + m * 128 + ((kc ^ (m & 7)) << 4);            \
            asm volatile("st.shared.v4.b32 [%0], {%1,%2,%3,%4};"                   \
                         :: "r"(dst), "r"(w0), "r"(w1), "r"(w2), "r"(w3));         \
        }                                                                          \
    } while (0)

    ISSUE_B(0, base);

    // ---- prologue: pure loads ----
    int P = g_Pg;
    int nch = (P + KC - 1) / KC; if (nch < 1) nch = 1;
    for (int i = t; i < PPAD; i += 256) s_pm[i] = g_pm[i];
    if (t < 64) { s_bits[t] = g_bits[m0 + t]; s_scale[t] = g_scale[m0 + t]; }
    if (t < HH) s_bias[t] = bias[t];
    __syncthreads();

    float acc[2][8][4];
    #pragma unroll
    for (int i = 0; i < 2; ++i)
        #pragma unroll
        for (int j = 0; j < 8; ++j)
            #pragma unroll
            for (int q = 0; q < 4; ++q) acc[i][j][q] = 0.f;

    BUILD_A(0, base);
    asm volatile("cp.async.wait_group 0;" ::: "memory");
    __syncthreads();

    for (int c = 0; c < nch; ++c) {
        uint32_t cur = base + (c & 1) * BUFB;
        if (c + 1 < nch) {
            uint32_t nxt = base + ((c + 1) & 1) * BUFB;
            ISSUE_B(c + 1, nxt);
            BUILD_A(c + 1, nxt);
        }
        uint32_t Ab = cur, Bb = cur + ABYTES;
        #pragma unroll
        for (int ks = 0; ks < 4; ++ks) {
            uint32_t a[2][4];
            #pragma unroll
            for (int mi = 0; mi < 2; ++mi) {
                int arow = wm + mi * 16 + (lane & 7) + ((lane >> 3) & 1) * 8;
                int akc = ks * 2 + (lane >> 4);
                uint32_t ad = Ab + arow * 128 + ((akc ^ (arow & 7)) << 4);
                LDSM4(a[mi][0], a[mi][1], a[mi][2], a[mi][3], ad);
            }
            #pragma unroll
            for (int nb2 = 0; nb2 < 4; ++nb2) {
                int brow = wn + nb2 * 16 + (lane & 7) + (lane >> 4) * 8;
                int bkc = ks * 2 + ((lane >> 3) & 1);
                uint32_t off = brow * 128 + ((bkc ^ (brow & 7)) << 4);
                uint32_t b0, b1, b2, b3;
                LDSM4(b0, b1, b2, b3, Bb + off);
                #pragma unroll
                for (int mi = 0; mi < 2; ++mi) {
                    MMA_F16(acc[mi][nb2 * 2 + 0], a[mi], b0, b1);
                    MMA_F16(acc[mi][nb2 * 2 + 1], a[mi], b2, b3);
                }
            }
        }
        if (c + 1 < nch) {
            asm volatile("cp.async.wait_group 0;" ::: "memory");
        }
        __syncthreads();
    }

    // ---- epilogue: scale by 1/cnt, add bias, store ----
    #pragma unroll
    for (int mi = 0; mi < 2; ++mi) {
        int rl = wm + mi * 16 + (lane >> 2);
        int row0 = m0 + rl;
        float sc0 = s_scale[rl];
        float sc1 = s_scale[rl + 8];
        #pragma unroll
        for (int nf = 0; nf < 8; ++nf) {
            int col = wn + (nf >> 1) * 16 + (nf & 1) * 8 + 2 * (lane & 3);
            float bv0 = s_bias[col], bv1 = s_bias[col + 1];
            float2 o0, o1;
            o0.x = acc[mi][nf][0] * sc0 + bv0;
            o0.y = acc[mi][nf][1] * sc0 + bv1;
            o1.x = acc[mi][nf][2] * sc1 + bv0;
            o1.y = acc[mi][nf][3] * sc1 + bv1;
            *(float2*)(out + (size_t)row0 * HH + col) = o0;
            *(float2*)(out + (size_t)(row0 + 8) * HH + col) = o1;
        }
    }
}

// ---------------- launch ----------------
extern "C" void kernel_launch(void* const* d_in, const int* in_sizes, int n_in,
                              void* d_out, int out_size) {
    const void* mask = d_in[0];                    // [64,256,40] bool
    const float* E = (const float*)d_in[1];        // [40,40,768] f32
    const void* avail = (const void*)d_in[2];      // [40,40] bool
    const float* W = (const float*)d_in[3];        // [256,768] f32
    const float* bias = (const float*)d_in[4];     // [256] f32
    float* out = (float*)d_out;                    // [64,256,256] f32

    cudaFuncSetAttribute(gemm_kernel, cudaFuncAttributeMaxDynamicSharedMemorySize,
                         DSMEM_BYTES);

    ew_kernel<<<dim3(104, 12), 64>>>(E, W, avail, (const unsigned int*)mask);
    gemm_kernel<<<BT_TOTAL / 64, 256, DSMEM_BYTES>>>(bias, out);
}